// round 8
// baseline (speedup 1.0000x reference)
#include <cuda_runtime.h>

#define NBATCH 256
#define NTIME  256
#define NS     512   // state size
#define NE     128   // embedding
#define NALPH  128   // alphabet / output
#define FAN    640   // NE + NS
#define BT     (NBATCH * NTIME)

#define NROWT  16    // row tiles (16 batch rows each)
#define NCOLT  8     // col tiles (64 state cols each)

typedef unsigned long long u64;

// ---- scratch (static __device__: allocation-free per harness rules) ----
__device__ float g_fin[BT * NS];          // fin[(b*NTIME+t)*NS + n]
__device__ float g_states[BT * NS];       // states[(b*NTIME+t)*NS + n]
__device__ int   g_flag[NTIME * NROWT * NCOLT];  // per-(step,rowtile,producer) ready flags

// ---- packed fp32x2 helpers (Blackwell FFMA2) ----
__device__ __forceinline__ void fma2(u64& d, u64 a, u64 b) {
    asm("fma.rn.f32x2 %0, %1, %2, %0;" : "+l"(d) : "l"(a), "l"(b));
}
__device__ __forceinline__ float hadd2(u64 v) {
    float lo, hi;
    asm("mov.b64 {%0,%1}, %2;" : "=f"(lo), "=f"(hi) : "l"(v));
    return lo + hi;
}

// ---- acquire/release flag ops ----
__device__ __forceinline__ int ld_acq(const int* p) {
    int v;
    asm volatile("ld.global.acquire.gpu.b32 %0, [%1];" : "=r"(v) : "l"(p) : "memory");
    return v;
}
__device__ __forceinline__ void st_rel(int* p, int v) {
    asm volatile("st.global.release.gpu.b32 [%0], %1;" :: "l"(p), "r"(v) : "memory");
}

// =====================================================================
// reset: zero flags (fresh per launch -> graph-replay safe)
// =====================================================================
__global__ void reset_kernel() {
    int i = blockIdx.x * blockDim.x + threadIdx.x;
    if (i < NTIME * NROWT * NCOLT) g_flag[i] = 0;
}

// =====================================================================
// Phase 1: fin[bt][n] = dot(emb[w[bt]], W_in[n][0:128]) + b_in[n]
// =====================================================================
__global__ void __launch_bounds__(256)
fin_kernel(const int* __restrict__ w,
           const float* __restrict__ emb,
           const float* __restrict__ W_in,
           const float* __restrict__ b_in) {
    __shared__ int   widx[64];
    __shared__ float As[64 * 36];
    __shared__ float Bs[64 * 33];

    int tid = threadIdx.x;
    int tx = tid & 15, ty = tid >> 4;
    int bt0 = blockIdx.x * 64;
    int n0  = blockIdx.y * 64;

    if (tid < 64) widx[tid] = w[bt0 + tid];
    __syncthreads();

    float acc[4][4] = {};

    for (int kc = 0; kc < NE; kc += 32) {
        for (int s = tid; s < 512; s += 256) {
            int row = s >> 3, q = (s & 7) << 2;
            float4 v = *(const float4*)&emb[widx[row] * NE + kc + q];
            *(float4*)&As[row * 36 + q] = v;
        }
        for (int s = tid; s < 512; s += 256) {
            int row = s >> 3, q = (s & 7) << 2;
            float4 v = *(const float4*)&W_in[(n0 + row) * FAN + kc + q];
            float* d = &Bs[row * 33 + q];
            d[0] = v.x; d[1] = v.y; d[2] = v.z; d[3] = v.w;
        }
        __syncthreads();
        #pragma unroll
        for (int k = 0; k < 32; ++k) {
            float a[4], b[4];
            #pragma unroll
            for (int i = 0; i < 4; ++i) a[i] = As[(ty + 16 * i) * 36 + k];
            #pragma unroll
            for (int j = 0; j < 4; ++j) b[j] = Bs[(tx + 16 * j) * 33 + k];
            #pragma unroll
            for (int i = 0; i < 4; ++i)
                #pragma unroll
                for (int j = 0; j < 4; ++j)
                    acc[i][j] = fmaf(a[i], b[j], acc[i][j]);
        }
        __syncthreads();
    }

    #pragma unroll
    for (int i = 0; i < 4; ++i) {
        int r = bt0 + ty + 16 * i;
        #pragma unroll
        for (int j = 0; j < 4; ++j) {
            int c = n0 + tx + 16 * j;
            g_fin[r * NS + c] = acc[i][j] + b_in[c];
        }
    }
}

// =====================================================================
// Phase 2: persistent recurrent kernel, chunk-pipelined state exchange.
// 128 blocks: rowtile = bid>>3, coltile = bid&7. 256 threads.
// Per step: GEMM proceeds chunk-by-chunk over the 8 producer strips of
// state[t-1]; own chunk is in SMEM already (epilogue STS), peer chunk
// i+1 is polled+prefetched (acquire flag) while chunk i is multiplied.
// =====================================================================
__global__ void __launch_bounds__(256, 1)
rnn_kernel(const float* __restrict__ W_in) {
    extern __shared__ float sm[];
    float* Bs = sm;                 // [64][516]  W_s slice
    float* As = sm + 64 * 516;      // [16][520]  state tile (all 512 cols)

    const int tid  = threadIdx.x;
    const int wrp  = tid >> 5;      // 0..7
    const int lane = tid & 31;
    const int tx   = lane & 7;      // 0..7 (col within warp's 8-col strip)
    const int tyq  = lane >> 3;     // 0..3 (row quadrant)
    const int rowtile = blockIdx.x >> 3;   // 0..15
    const int coltile = blockIdx.x & 7;    // 0..7
    const int rb0 = rowtile * 16;
    const int cb0 = coltile * 64;

    // Load W_s slice once: Bs[n][k] = W_in[(cb0+n)*FAN + NE + k]
    for (int s = tid; s < 64 * 128; s += 256) {
        int row = s >> 7, q = (s & 127) << 2;
        float4 v = *(const float4*)&W_in[(cb0 + row) * FAN + NE + q];
        *(float4*)&Bs[row * 516 + q] = v;
    }
    __syncthreads();

    const int mycol = 8 * wrp + tx;             // 0..63 within tile
    const float* bp  = Bs + mycol * 516;
    const float* ap0 = As + (tyq)      * 520;
    const float* ap1 = As + (tyq + 4)  * 520;
    const float* ap2 = As + (tyq + 8)  * 520;
    const float* ap3 = As + (tyq + 12) * 520;

    const int cg = cb0 + mycol;                 // global state col
    int rr[4];
    rr[0] = rb0 + tyq; rr[1] = rb0 + tyq + 4;
    rr[2] = rb0 + tyq + 8; rr[3] = rb0 + tyq + 12;

    // staging mapping: one float4 per thread per 16x64 chunk
    const int srow  = tid >> 4;          // 0..15
    const int scol4 = (tid & 15) << 2;   // 0..60

    // prefetch fin for t = 0
    float ffin[4];
    #pragma unroll
    for (int i = 0; i < 4; ++i)
        ffin[i] = __ldcg(&g_fin[(rr[i] * NTIME + 0) * NS + cg]);

    for (int t = 0; t < NTIME; ++t) {
        u64 acc[4] = {};

        if (t > 0) {
            float4 nxt = make_float4(0.f, 0.f, 0.f, 0.f);
            #pragma unroll 1
            for (int idx = 0; idx < NCOLT; ++idx) {
                const int cc = (coltile + idx) & 7;
                if (idx > 0) {
                    // stage prefetched peer chunk
                    *(float4*)&As[srow * 520 + cc * 64 + scol4] = nxt;
                }
                __syncthreads();    // chunk cc visible to all warps
                if (idx + 1 < NCOLT) {
                    // poll producer of next chunk, prefetch (overlaps GEMM)
                    const int ncc = (coltile + idx + 1) & 7;
                    const int* fl = &g_flag[((t - 1) * NROWT + rowtile) * NCOLT + ncc];
                    while (ld_acq(fl) == 0) { }
                    nxt = __ldcg((const float4*)
                        &g_states[((rb0 + srow) * NTIME + (t - 1)) * NS + ncc * 64 + scol4]);
                }
                // GEMM over k in [cc*64, cc*64+64)
                const int kb = cc << 6;
                const float* bk  = bp  + kb;
                const float* a0k = ap0 + kb;
                const float* a1k = ap1 + kb;
                const float* a2k = ap2 + kb;
                const float* a3k = ap3 + kb;
                #pragma unroll
                for (int k = 0; k < 64; k += 4) {
                    ulonglong2 B  = *(const ulonglong2*)(bk  + k);
                    ulonglong2 A0 = *(const ulonglong2*)(a0k + k);
                    ulonglong2 A1 = *(const ulonglong2*)(a1k + k);
                    ulonglong2 A2 = *(const ulonglong2*)(a2k + k);
                    ulonglong2 A3 = *(const ulonglong2*)(a3k + k);
                    fma2(acc[0], A0.x, B.x); fma2(acc[0], A0.y, B.y);
                    fma2(acc[1], A1.x, B.x); fma2(acc[1], A1.y, B.y);
                    fma2(acc[2], A2.x, B.x); fma2(acc[2], A2.y, B.y);
                    fma2(acc[3], A3.x, B.x); fma2(acc[3], A3.y, B.y);
                }
            }
        }

        // ---- epilogue: tanh(acc + fin_t) ----
        // own chunk -> SMEM directly (next step's idx=0 input, no global wait)
        // all values -> g_states log (for peers' staging + out_kernel)
        #pragma unroll
        for (int i = 0; i < 4; ++i) {
            float v = tanhf(hadd2(acc[i]) + ffin[i]);
            As[(tyq + 4 * i) * 520 + cg] = v;   // cg = cb0 + mycol (own region)
            g_states[(rr[i] * NTIME + t) * NS + cg] = v;
        }
        __syncthreads();    // all STG issued+ordered (CTA), own STS visible

        if (t + 1 < NTIME) {
            if (tid == 0) {
                __threadfence();   // make this block's state[t] globally visible
                st_rel(&g_flag[(t * NROWT + rowtile) * NCOLT + coltile], 1);
            }
            // prefetch fin(t+1) — overlaps the whole next chunk loop
            #pragma unroll
            for (int i = 0; i < 4; ++i)
                ffin[i] = __ldcg(&g_fin[(rr[i] * NTIME + t + 1) * NS + cg]);
        }
    }
}

// =====================================================================
// Phase 3: y[bt][a] = dot(states[bt], W_out[a]) + b_out[a]
// =====================================================================
__global__ void __launch_bounds__(256)
out_kernel(const float* __restrict__ W_out,
           const float* __restrict__ b_out,
           float* __restrict__ y) {
    __shared__ float As[64 * 36];
    __shared__ float Bs[64 * 33];

    int tid = threadIdx.x;
    int tx = tid & 15, ty = tid >> 4;
    int bt0 = blockIdx.x * 64;
    int a0  = blockIdx.y * 64;

    float acc[4][4] = {};

    for (int kc = 0; kc < NS; kc += 32) {
        for (int s = tid; s < 512; s += 256) {
            int row = s >> 3, q = (s & 7) << 2;
            float4 v = *(const float4*)&g_states[(bt0 + row) * NS + kc + q];
            *(float4*)&As[row * 36 + q] = v;
        }
        for (int s = tid; s < 512; s += 256) {
            int row = s >> 3, q = (s & 7) << 2;
            float4 v = *(const float4*)&W_out[(a0 + row) * NS + kc + q];
            float* d = &Bs[row * 33 + q];
            d[0] = v.x; d[1] = v.y; d[2] = v.z; d[3] = v.w;
        }
        __syncthreads();
        #pragma unroll
        for (int k = 0; k < 32; ++k) {
            float a[4], b[4];
            #pragma unroll
            for (int i = 0; i < 4; ++i) a[i] = As[(ty + 16 * i) * 36 + k];
            #pragma unroll
            for (int j = 0; j < 4; ++j) b[j] = Bs[(tx + 16 * j) * 33 + k];
            #pragma unroll
            for (int i = 0; i < 4; ++i)
                #pragma unroll
                for (int j = 0; j < 4; ++j)
                    acc[i][j] = fmaf(a[i], b[j], acc[i][j]);
        }
        __syncthreads();
    }

    #pragma unroll
    for (int i = 0; i < 4; ++i) {
        int r = bt0 + ty + 16 * i;
        #pragma unroll
        for (int j = 0; j < 4; ++j) {
            int c = a0 + tx + 16 * j;
            y[r * NALPH + c] = acc[i][j] + b_out[c];
        }
    }
}

// =====================================================================
// launch
// =====================================================================
extern "C" void kernel_launch(void* const* d_in, const int* in_sizes, int n_in,
                              void* d_out, int out_size) {
    const int*   w     = (const int*)  d_in[0];
    const float* emb   = (const float*)d_in[1];
    const float* W_in  = (const float*)d_in[2];
    const float* b_in  = (const float*)d_in[3];
    const float* W_out = (const float*)d_in[4];
    const float* b_out = (const float*)d_in[5];
    float* y = (float*)d_out;

    size_t rnn_smem = (size_t)(64 * 516 + 16 * 520) * sizeof(float);
    cudaFuncSetAttribute(rnn_kernel,
                         cudaFuncAttributeMaxDynamicSharedMemorySize,
                         (int)rnn_smem);

    reset_kernel<<<(NTIME * NROWT * NCOLT + 255) / 256, 256>>>();
    fin_kernel<<<dim3(BT / 64, NS / 64), 256>>>(w, emb, W_in, b_in);
    rnn_kernel<<<128, 256, rnn_smem>>>(W_in);
    out_kernel<<<dim3(BT / 64, NALPH / 64), 256>>>(W_out, b_out, y);
}